// round 14
// baseline (speedup 1.0000x reference)
#include <cuda_runtime.h>
#include <math.h>

#define Bsz  2048
#define Nn_  200
#define FILLV (-10000.0f)
#define NCTA 592                           // 4 CTAs/SM x 148 SMs, one wave
#define NTASK (Bsz * 8)                    // octant tasks

// ---------------- device scratch ----------------
__device__ float g_WmT[256 * 256];
__device__ float g_Wkm[256 * 256];        // Wk @ Wm^T
__device__ float g_Wgfull[512 * 256];     // [Wg_top ; Wm @ Wg_bot]
__device__ float g_Wmt[256 * 256];        // Wm @ Wt
__device__ float g_cat[Bsz * 512];        // [:,0:256]=m_init  [:,256:512]=c
__device__ float g_v  [Bsz * 256];
__device__ float g_mo [Bsz * 256];
__device__ float g_y  [Bsz * 512];
__device__ float2 g_pm[Bsz * 8];          // per-octant (max, sumexp)
__device__ float g_pc[Bsz * 8 * 256];     // per-octant partial c (unnormalized)
__device__ int   g_flags[4];              // OR-only, idempotent across replays

// ---------------- async-copy helpers ----------------
__device__ __forceinline__ void cp16(void* dst, const void* src) {
    unsigned sa = (unsigned)__cvta_generic_to_shared(dst);
    asm volatile("cp.async.cg.shared.global [%0], [%1], 16;" ::"r"(sa), "l"(src) : "memory");
}
__device__ __forceinline__ void cp_commit() { asm volatile("cp.async.commit_group;" ::: "memory"); }
__device__ __forceinline__ void cp_wait0()  { asm volatile("cp.async.wait_group 0;" ::: "memory"); }
__device__ __forceinline__ void cp_wait1()  { asm volatile("cp.async.wait_group 1;" ::: "memory"); }

__device__ __forceinline__ void mbar_init(unsigned mbar, unsigned count) {
    asm volatile("mbarrier.init.shared.b64 [%0], %1;" ::"r"(mbar), "r"(count) : "memory");
}
__device__ __forceinline__ void mbar_expect_tx(unsigned mbar, unsigned bytes) {
    asm volatile("mbarrier.arrive.expect_tx.shared.b64 _, [%0], %1;" ::"r"(mbar), "r"(bytes) : "memory");
}
__device__ __forceinline__ void tma_bulk_1d(unsigned sdst, const void* gsrc, unsigned bytes, unsigned mbar) {
    asm volatile("cp.async.bulk.shared::cta.global.mbarrier::complete_tx::bytes [%0], [%1], %2, [%3];"
                 ::"r"(sdst), "l"(gsrc), "r"(bytes), "r"(mbar) : "memory");
}
__device__ __forceinline__ void mbar_wait_par(unsigned mbar, int parity) {
    asm volatile(
        "{\n\t.reg .pred P;\n\t"
        "LAB_WAIT%=:\n\t"
        "mbarrier.try_wait.parity.acquire.cta.shared::cta.b64 P, [%0], %1, 0x989680;\n\t"
        "@P bra.uni LAB_DONE%=;\n\t"
        "bra.uni LAB_WAIT%=;\n\t"
        "LAB_DONE%=:\n\t}"
        ::"r"(mbar), "r"(parity) : "memory");
}

#define ZERO84(a) {_Pragma("unroll") for(int i=0;i<8;i++) _Pragma("unroll") for(int j=0;j<4;j++) a[i][j]=0.f;}
#define ZERO44(a) {_Pragma("unroll") for(int i=0;i<4;i++) _Pragma("unroll") for(int j=0;j<4;j++) a[i][j]=0.f;}
#define FMA4(r, av, bv) { (r)[0]=fmaf((av),(bv).x,(r)[0]); (r)[1]=fmaf((av),(bv).y,(r)[1]); \
                          (r)[2]=fmaf((av),(bv).z,(r)[2]); (r)[3]=fmaf((av),(bv).w,(r)[3]); }

// ---------------- 128x64x16 double-buffered fp32 mainloop ----------------
__device__ __forceinline__ void gemm_mainloop128(
    const float* __restrict__ A, int lda,
    const float* __restrict__ B, int ldb,
    int K, int m0, int n0, float acc[8][4])
{
    __shared__ float As[2][128][20];
    __shared__ float Bs[2][16][68];
    const int t = threadIdx.x;
    const int arow = t >> 2, ac4 = (t & 3) * 4;
    const int brow = t >> 4, bc4 = (t & 15) * 4;
    const int tx = t & 15, ty = t >> 4;
    const float* Ag0 = A + (size_t)(m0 + arow) * lda + ac4;
    const float* Ag1 = A + (size_t)(m0 + arow + 64) * lda + ac4;
    const float* Bg  = B + (size_t)brow * ldb + n0 + bc4;

    cp16(&As[0][arow][ac4],      Ag0);
    cp16(&As[0][arow + 64][ac4], Ag1);
    cp16(&Bs[0][brow][bc4],      Bg);
    cp_commit();
    const int nIt = K / 16;
    for (int it = 0; it < nIt; ++it) {
        const int st = it & 1;
        if (it + 1 < nIt) {
            cp16(&As[st ^ 1][arow][ac4],      Ag0 + (it + 1) * 16);
            cp16(&As[st ^ 1][arow + 64][ac4], Ag1 + (it + 1) * 16);
            cp16(&Bs[st ^ 1][brow][bc4],      Bg + (size_t)(it + 1) * 16 * ldb);
            cp_commit();
            cp_wait1();
        } else cp_wait0();
        __syncthreads();
#pragma unroll
        for (int kq = 0; kq < 16; kq += 4) {
            float4 b[4];
#pragma unroll
            for (int kk = 0; kk < 4; kk++) b[kk] = *(const float4*)&Bs[st][kq + kk][tx * 4];
#pragma unroll
            for (int i = 0; i < 8; i++) {
                float4 a = *(const float4*)&As[st][ty * 8 + i][kq];
                FMA4(acc[i], a.x, b[0]);
                FMA4(acc[i], a.y, b[1]);
                FMA4(acc[i], a.z, b[2]);
                FMA4(acc[i], a.w, b[3]);
            }
        }
        __syncthreads();
    }
}

// 64x64 compute (gemm2 only)
__device__ __forceinline__ void compute16(
    const float (*__restrict__ A)[20], const float (*__restrict__ Bm)[68],
    int ty, int tx, float acc[4][4])
{
#pragma unroll
    for (int kq = 0; kq < 16; kq += 4) {
        float4 a[4], b[4];
#pragma unroll
        for (int i = 0; i < 4; i++) a[i] = *(const float4*)&A[ty * 4 + i][kq];
#pragma unroll
        for (int kk = 0; kk < 4; kk++) b[kk] = *(const float4*)&Bm[kq + kk][tx * 4];
#pragma unroll
        for (int i = 0; i < 4; i++) {
            FMA4(acc[i], a[i].x, b[0]);
            FMA4(acc[i], a[i].y, b[1]);
            FMA4(acc[i], a[i].z, b[2]);
            FMA4(acc[i], a[i].w, b[3]);
        }
    }
}
__device__ __forceinline__ void compute16_dual(
    const float (*__restrict__ A)[20], const float (*__restrict__ B1)[68],
    const float (*__restrict__ B2)[68],
    int ty, int tx, float accg[4][4], float acct[4][4])
{
#pragma unroll
    for (int kq = 0; kq < 16; kq += 4) {
        float4 a[4], b[4], c[4];
#pragma unroll
        for (int i = 0; i < 4; i++) a[i] = *(const float4*)&A[ty * 4 + i][kq];
#pragma unroll
        for (int kk = 0; kk < 4; kk++) {
            b[kk] = *(const float4*)&B1[kq + kk][tx * 4];
            c[kk] = *(const float4*)&B2[kq + kk][tx * 4];
        }
#pragma unroll
        for (int i = 0; i < 4; i++) {
            FMA4(accg[i], a[i].x, b[0]);
            FMA4(accg[i], a[i].y, b[1]);
            FMA4(accg[i], a[i].z, b[2]);
            FMA4(accg[i], a[i].w, b[3]);
            FMA4(acct[i], a[i].x, c[0]);
            FMA4(acct[i], a[i].y, c[1]);
            FMA4(acct[i], a[i].z, c[2]);
            FMA4(acct[i], a[i].w, c[3]);
        }
    }
}

// ---------------- prep: tiled transpose Wm, copy Wg top, detect mask layout ----------------
__global__ void prep_k(const float* __restrict__ Wm, const float* __restrict__ Wg,
                       const unsigned* __restrict__ mp) {
    __shared__ float S[32][33];
    int bid = blockIdx.x, t = threadIdx.x;
    if (bid < 64) {
        int tr = bid >> 3, tc = bid & 7;
        int r = t >> 3, c4 = (t & 7) * 4;
        float4 v = *(const float4*)&Wm[(size_t)(tr * 32 + r) * 256 + tc * 32 + c4];
        S[r][c4 + 0] = v.x; S[r][c4 + 1] = v.y; S[r][c4 + 2] = v.z; S[r][c4 + 3] = v.w;
        __syncthreads();
        float4 o;
        o.x = S[c4 + 0][r]; o.y = S[c4 + 1][r]; o.z = S[c4 + 2][r]; o.w = S[c4 + 3][r];
        *(float4*)&g_WmT[(size_t)(tc * 32 + r) * 256 + tr * 32 + c4] = o;
    } else if (bid < 128) {
        int idx = (bid - 64) * 1024 + t * 4;
        *(float4*)&g_Wgfull[idx] = *(const float4*)&Wg[idx];
    } else {
        unsigned m = 0;
        for (int i = (bid - 128) * 256 + t; i < 102400; i += 64 * 256) {
            unsigned wv = mp[i];
            if (wv & 0x000000FFu) m |= 1;
            if (wv & 0x0000FF00u) m |= 2;
            if (wv & 0x00FF0000u) m |= 4;
            if (wv & 0xFF000000u) m |= 8;
        }
#pragma unroll
        for (int o = 16; o > 0; o >>= 1) m |= __shfl_down_sync(0xffffffffu, m, o);
        if ((t & 31) == 0 && m) {
            if (m & 1) atomicOr(&g_flags[0], 1);
            if (m & 2) atomicOr(&g_flags[1], 1);
            if (m & 4) atomicOr(&g_flags[2], 1);
            if (m & 8) atomicOr(&g_flags[3], 1);
        }
    }
}

// ---------------- pre_all: m_init GEMM + 3 weight-fold GEMMs in one launch ----------------
__global__ void __launch_bounds__(256) pre_all_k(
    const float* __restrict__ r_emb, const float* __restrict__ Wi,
    const float* __restrict__ bi, const float* __restrict__ Wk,
    const float* __restrict__ Wm, const float* __restrict__ Wg,
    const float* __restrict__ Wt)
{
    const int yy = blockIdx.y;
    const float* A; const float* B; float* C; int ldc, m0;
    const float* bias = nullptr;
    if (yy < 16)      { A = r_emb; B = Wi;         C = g_cat;            ldc = 512; m0 = yy * 128; bias = bi; }
    else if (yy < 18) { A = Wk;    B = g_WmT;      C = g_Wkm;            ldc = 256; m0 = (yy - 16) * 128; }
    else if (yy < 20) { A = Wm;    B = Wg + 65536; C = g_Wgfull + 65536; ldc = 256; m0 = (yy - 18) * 128; }
    else              { A = Wm;    B = Wt;         C = g_Wmt;            ldc = 256; m0 = (yy - 20) * 128; }
    const int n0 = blockIdx.x * 64;
    float acc[8][4]; ZERO84(acc);
    gemm_mainloop128(A, 256, B, 256, 256, m0, n0, acc);
    const int tx = threadIdx.x & 15, ty = threadIdx.x >> 4;
#pragma unroll
    for (int i = 0; i < 8; i++) {
        int gm = m0 + ty * 8 + i;
#pragma unroll
        for (int j = 0; j < 4; j++) {
            int gn = n0 + tx * 4 + j;
            float v = acc[i][j];
            if (bias) v += bias[gn];
            C[(size_t)gm * ldc + gn] = v;
        }
    }
}

// ---------------- gemm1b: v = m_init @ Wkm ----------------
__global__ void __launch_bounds__(256) gemm1b_k() {
    int m0 = blockIdx.y * 128, n0 = blockIdx.x * 64;
    float acc[8][4]; ZERO84(acc);
    gemm_mainloop128(g_cat, 512, g_Wkm, 256, 256, m0, n0, acc);
    const int tx = threadIdx.x & 15, ty = threadIdx.x >> 4;
#pragma unroll
    for (int i = 0; i < 8; i++)
#pragma unroll
        for (int j = 0; j < 4; j++)
            g_v[(size_t)(m0 + ty * 8 + i) * 256 + n0 + tx * 4 + j] = acc[i][j];
}

// ---------------- attention: persistent CTAs, double-buffered TMA prefetch ----------------
// 592 CTAs (one wave, 4/SM). Each stride-loops over 16384 octant tasks (25 rows each).
__global__ void __launch_bounds__(256) attn_part_k(
    const float* __restrict__ nb_rel,
    const float* __restrict__ delta_t,
    const void*  __restrict__ maskp,
    const float* __restrict__ lgam)
{
    extern __shared__ float TILE2[];                // 2 x 25x256 fp32 = 51200 B
    __shared__ float SA[28];
    __shared__ float RED[256];
    __shared__ __align__(8) unsigned long long MB[2];
    const int t = threadIdx.x;
    const int w = t >> 5, l = t & 31;

    const unsigned tile_s = (unsigned)__cvta_generic_to_shared(TILE2);
    const unsigned mb_s   = (unsigned)__cvta_generic_to_shared(MB);

    if (t == 0) {
        mbar_init(mb_s, 1);
        mbar_init(mb_s + 8, 1);
        asm volatile("fence.proxy.async.shared::cta;" ::: "memory");
    }
    __syncthreads();

    float gamma = expf(lgam[0]);
    int f0 = g_flags[0], f1 = g_flags[1], f2 = g_flags[2], f3 = g_flags[3];
    int mode = f1 ? 0 : ((f2 | f3) ? 2 : (f0 ? 1 : 0));

    const int task0 = blockIdx.x;
    // prologue: prefetch first task into buf 0
    if (t == 0 && task0 < NTASK) {
        mbar_expect_tx(mb_s, 25600u);
        tma_bulk_1d(tile_s, (const char*)nb_rel + (size_t)task0 * 25600u, 25600u, mb_s);
    }

    int ph[2] = {0, 0};
    int it = 0;
    for (int task = task0; task < NTASK; task += NCTA, ++it) {
        const int cur = it & 1;
        // prefetch next task into the other buffer (safe: its readers synced last iter)
        const int nxt = task + NCTA;
        if (t == 0 && nxt < NTASK) {
            unsigned mbn = mb_s + (unsigned)(cur ^ 1) * 8u;
            mbar_expect_tx(mbn, 25600u);
            tma_bulk_1d(tile_s + (unsigned)(cur ^ 1) * 25600u,
                        (const char*)nb_rel + (size_t)nxt * 25600u, 25600u, mbn);
        }
        // wait current buffer
        mbar_wait_par(mb_s + (unsigned)cur * 8u, ph[cur]);
        ph[cur] ^= 1;
        const float* TILE = TILE2 + cur * 6400;

        const int b = task >> 3, oct = task & 7;
        float vr[8];
#pragma unroll
        for (int k = 0; k < 8; k++) vr[k] = g_v[(size_t)b * 256 + k * 32 + l];

        // dots: warp w rows (w0: 4, w1..7: 3)
        {
            const int cnt = (w == 0) ? 4 : 3;
            const int base = (w == 0) ? 0 : 3 * w + 1;
            for (int j = 0; j < cnt; j++) {
                int n = base + j;
                float s = 0.f;
#pragma unroll
                for (int k = 0; k < 8; k++)
                    s = fmaf(TILE[n * 256 + k * 32 + l], vr[k], s);
#pragma unroll
                for (int o = 16; o > 0; o >>= 1) s += __shfl_down_sync(0xffffffffu, s, o);
                if (l == 0) SA[n] = s * 0.0625f;    // 1/sqrt(256)
            }
        }
        __syncthreads();

        // local av: masked rows get FILLV (exact partial-softmax semantics)
        float av = FILLV;
        if (t < 25) {
            size_t mi = (size_t)b * Nn_ + oct * 25 + t;
            int m;
            if (mode == 0)      m = ((const unsigned char*)maskp)[mi] != 0;
            else if (mode == 1) m = ((const int*)maskp)[mi] != 0;
            else                m = (((const float*)maskp)[mi] != 0.f);
            if (m) {
                float term = fmaxf(-gamma * fmaxf(delta_t[mi], 0.f), -10.f);
                av = SA[t] + term;
            }
        }
        RED[t] = (t < 25) ? av : -1e30f;
        __syncthreads();
        for (int s = 128; s > 0; s >>= 1) { if (t < s) RED[t] = fmaxf(RED[t], RED[t + s]); __syncthreads(); }
        float m0 = RED[0];
        __syncthreads();
        float ex = (t < 25) ? expf(av - m0) : 0.f;
        RED[t] = ex;
        __syncthreads();
        for (int s = 128; s > 0; s >>= 1) { if (t < s) RED[t] += RED[t + s]; __syncthreads(); }
        float s0 = RED[0];
        if (t < 25) SA[t] = ex;                     // unnormalized weights
        __syncthreads();

        // partial c over 25 rows (unnormalized)
        float c0 = 0.f;
#pragma unroll 5
        for (int n = 0; n < 25; n++)
            c0 = fmaf(SA[n], TILE[n * 256 + t], c0);
        g_pc[(size_t)task * 256 + t] = c0;
        if (t == 0) g_pm[task] = make_float2(m0, s0);
        __syncthreads();                            // all TILE reads done before overwrite
    }
}

// ---------------- attention part 2: combine 8 octants exactly ----------------
__global__ void __launch_bounds__(256) attn_fin_k() {
    const int b = blockIdx.x, t = threadIdx.x;
    float2 p[8];
#pragma unroll
    for (int i = 0; i < 8; i++) p[i] = g_pm[8 * b + i];
    float M = -1e30f;
#pragma unroll
    for (int i = 0; i < 8; i++) M = fmaxf(M, p[i].x);
    float den = 0.f, num = 0.f;
#pragma unroll
    for (int i = 0; i < 8; i++) {
        float sc = expf(p[i].x - M);
        den = fmaf(sc, p[i].y, den);
        num = fmaf(sc, g_pc[(size_t)(8 * b + i) * 256 + t], num);
    }
    g_cat[(size_t)b * 512 + 256 + t] = num / den;
}

// ---------------- GEMM2: gg = cat@Wgf (K=512) & t = c@Wmt (K=256), gate epilogue ----------------
__global__ void __launch_bounds__(256) gemm2_k(
    const float* __restrict__ bg, const float* __restrict__ bt)
{
    __shared__ float As [2][64][20];
    __shared__ float B1s[2][16][68];
    __shared__ float B2s[2][16][68];
    const int t = threadIdx.x;
    const int arow = t >> 2, ac4 = (t & 3) * 4;
    const int brow = t >> 4, bc4 = (t & 15) * 4;
    const int tx = t & 15, ty = t >> 4;
    const int m0 = blockIdx.y * 64, n0 = blockIdx.x * 64;

    const float* Ag  = g_cat    + (size_t)(m0 + arow) * 512 + ac4;
    const float* B1g = g_Wgfull + (size_t)brow * 256 + n0 + bc4;
    const float* B2g = g_Wmt    + (size_t)brow * 256 + n0 + bc4;

    float accg[4][4], acct[4][4];
    ZERO44(accg); ZERO44(acct);

    cp16(&As[0][arow][ac4], Ag);
    cp16(&B1s[0][brow][bc4], B1g);
    cp_commit();
    const int nIt = 32;
    for (int it = 0; it < nIt; ++it) {
        const int st = it & 1;
        if (it + 1 < nIt) {
            int kb = (it + 1) * 16;
            cp16(&As[st ^ 1][arow][ac4], Ag + kb);
            cp16(&B1s[st ^ 1][brow][bc4], B1g + (size_t)kb * 256);
            if (kb >= 256)
                cp16(&B2s[st ^ 1][brow][bc4], B2g + (size_t)(kb - 256) * 256);
            cp_commit();
            cp_wait1();
        } else cp_wait0();
        __syncthreads();
        if (it < 16) compute16(As[st], B1s[st], ty, tx, accg);
        else         compute16_dual(As[st], B1s[st], B2s[st], ty, tx, accg, acct);
        __syncthreads();
    }

#pragma unroll
    for (int i = 0; i < 4; i++) {
        int gm = m0 + ty * 4 + i;
#pragma unroll
        for (int j = 0; j < 4; j++) {
            int gn = n0 + tx * 4 + j;
            float gate = 1.f / (1.f + expf(-(accg[i][j] + bg[gn])));
            float th = tanhf(acct[i][j] + bt[gn]);
            g_mo[(size_t)gm * 256 + gn] = gate * th + (1.f - gate) * g_cat[(size_t)gm * 512 + gn];
        }
    }
}

// ---------------- GEMM3: y = m_out @ Wo + bo ----------------
__global__ void __launch_bounds__(256) gemm3_k(
    const float* __restrict__ Wo, const float* __restrict__ bo)
{
    int m0 = blockIdx.y * 128, n0 = blockIdx.x * 64;
    float acc[8][4]; ZERO84(acc);
    gemm_mainloop128(g_mo, 256, Wo, 512, 256, m0, n0, acc);
    const int tx = threadIdx.x & 15, ty = threadIdx.x >> 4;
#pragma unroll
    for (int i = 0; i < 8; i++)
#pragma unroll
        for (int j = 0; j < 4; j++)
            g_y[(size_t)(m0 + ty * 8 + i) * 512 + n0 + tx * 4 + j] = acc[i][j] + bo[n0 + tx * 4 + j];
}

// ---------------- layernorm ----------------
__global__ void __launch_bounds__(256) ln_k(
    const float* __restrict__ g, const float* __restrict__ bta, float* __restrict__ out)
{
    __shared__ float RS[256], RQ[256];
    const int t = threadIdx.x, b = blockIdx.x;
    float a = g_y[(size_t)b * 512 + t];
    float c = g_y[(size_t)b * 512 + 256 + t];
    RS[t] = a + c;
    RQ[t] = a * a + c * c;
    __syncthreads();
    for (int s = 128; s > 0; s >>= 1) {
        if (t < s) { RS[t] += RS[t + s]; RQ[t] += RQ[t + s]; }
        __syncthreads();
    }
    float mu = RS[0] * (1.f / 512.f);
    float var = RQ[0] * (1.f / 512.f) - mu * mu;
    float inv = rsqrtf(var + 1e-5f);
    out[(size_t)b * 512 + t]       = (a - mu) * inv * g[t] + bta[t];
    out[(size_t)b * 512 + 256 + t] = (c - mu) * inv * g[t + 256] + bta[t + 256];
}

// ---------------- launch ----------------
extern "C" void kernel_launch(void* const* d_in, const int* in_sizes, int n_in,
                              void* d_out, int out_size) {
    const float* nb_rel  = (const float*)d_in[0];
    const float* delta_t = (const float*)d_in[1];
    const float* r_emb   = (const float*)d_in[2];
    const void*  maskp   = d_in[3];
    const float* Wi = (const float*)d_in[4];
    const float* bi = (const float*)d_in[5];
    const float* Wm = (const float*)d_in[6];
    const float* Wk = (const float*)d_in[7];
    const float* lg = (const float*)d_in[8];
    const float* Wg = (const float*)d_in[9];
    const float* bg = (const float*)d_in[10];
    const float* Wt = (const float*)d_in[11];
    const float* bt = (const float*)d_in[12];
    const float* Wo = (const float*)d_in[13];
    const float* bo = (const float*)d_in[14];
    const float* lng = (const float*)d_in[15];
    const float* lnb = (const float*)d_in[16];
    float* out = (float*)d_out;

    cudaFuncSetAttribute(attn_part_k, cudaFuncAttributeMaxDynamicSharedMemorySize, 51200);

    prep_k<<<192, 256>>>(Wm, Wg, (const unsigned*)maskp);
    pre_all_k<<<dim3(4, 22), 256>>>(r_emb, Wi, bi, Wk, Wm, Wg, Wt);
    gemm1b_k<<<dim3(4, 16), 256>>>();
    attn_part_k<<<NCTA, 256, 51200>>>(nb_rel, delta_t, maskp, lg);
    attn_fin_k<<<Bsz, 256>>>();
    gemm2_k<<<dim3(4, 32), 256>>>(bg, bt);
    gemm3_k<<<dim3(8, 16), 256>>>(Wo, bo);
    ln_k<<<Bsz, 256>>>(lng, lnb, out);
}

// round 15
// speedup vs baseline: 1.1376x; 1.1376x over previous
#include <cuda_runtime.h>
#include <math.h>

#define Bsz  2048
#define Nn_  200
#define FILLV (-10000.0f)

// ---------------- device scratch ----------------
__device__ float g_WmT[256 * 256];
__device__ float g_Wkm[256 * 256];        // Wk @ Wm^T
__device__ float g_Wgfull[512 * 256];     // [Wg_top ; Wm @ Wg_bot]
__device__ float g_Wmt[256 * 256];        // Wm @ Wt
__device__ float g_cat[Bsz * 512];        // [:,0:256]=m_init  [:,256:512]=c
__device__ float g_v  [Bsz * 256];
__device__ float g_mo [Bsz * 256];
__device__ float g_y  [Bsz * 512];
__device__ float2 g_pm[Bsz * 4];          // per-quarter (max, sumexp)
__device__ float g_pc[Bsz * 4 * 256];     // per-quarter partial c (unnormalized)
__device__ int   g_flags[4];              // OR-only, idempotent across replays

// ---------------- async-copy helpers ----------------
__device__ __forceinline__ void cp16(void* dst, const void* src) {
    unsigned sa = (unsigned)__cvta_generic_to_shared(dst);
    asm volatile("cp.async.cg.shared.global [%0], [%1], 16;" ::"r"(sa), "l"(src) : "memory");
}
__device__ __forceinline__ void cp_commit() { asm volatile("cp.async.commit_group;" ::: "memory"); }
__device__ __forceinline__ void cp_wait0()  { asm volatile("cp.async.wait_group 0;" ::: "memory"); }
__device__ __forceinline__ void cp_wait1()  { asm volatile("cp.async.wait_group 1;" ::: "memory"); }

__device__ __forceinline__ void mbar_init(unsigned mbar, unsigned count) {
    asm volatile("mbarrier.init.shared.b64 [%0], %1;" ::"r"(mbar), "r"(count) : "memory");
}
__device__ __forceinline__ void mbar_expect_tx(unsigned mbar, unsigned bytes) {
    asm volatile("mbarrier.arrive.expect_tx.shared.b64 _, [%0], %1;" ::"r"(mbar), "r"(bytes) : "memory");
}
__device__ __forceinline__ void tma_bulk_1d(unsigned sdst, const void* gsrc, unsigned bytes, unsigned mbar) {
    asm volatile("cp.async.bulk.shared::cta.global.mbarrier::complete_tx::bytes [%0], [%1], %2, [%3];"
                 ::"r"(sdst), "l"(gsrc), "r"(bytes), "r"(mbar) : "memory");
}
__device__ __forceinline__ void mbar_wait_p0(unsigned mbar) {
    asm volatile(
        "{\n\t.reg .pred P;\n\t"
        "LAB_WAIT%=:\n\t"
        "mbarrier.try_wait.parity.acquire.cta.shared::cta.b64 P, [%0], 0, 0x989680;\n\t"
        "@P bra.uni LAB_DONE%=;\n\t"
        "bra.uni LAB_WAIT%=;\n\t"
        "LAB_DONE%=:\n\t}"
        ::"r"(mbar) : "memory");
}

#define ZERO44(a) {_Pragma("unroll") for(int i=0;i<4;i++) _Pragma("unroll") for(int j=0;j<4;j++) a[i][j]=0.f;}
#define FMA4(r, av, bv) { (r)[0]=fmaf((av),(bv).x,(r)[0]); (r)[1]=fmaf((av),(bv).y,(r)[1]); \
                          (r)[2]=fmaf((av),(bv).z,(r)[2]); (r)[3]=fmaf((av),(bv).w,(r)[3]); }

// vectorized 16-k compute: A smem [64][20] (k inner), B smem [16][68]
__device__ __forceinline__ void compute16(
    const float (*__restrict__ A)[20], const float (*__restrict__ Bm)[68],
    int ty, int tx, float acc[4][4])
{
#pragma unroll
    for (int kq = 0; kq < 16; kq += 4) {
        float4 a[4], b[4];
#pragma unroll
        for (int i = 0; i < 4; i++) a[i] = *(const float4*)&A[ty * 4 + i][kq];
#pragma unroll
        for (int kk = 0; kk < 4; kk++) b[kk] = *(const float4*)&Bm[kq + kk][tx * 4];
#pragma unroll
        for (int i = 0; i < 4; i++) {
            FMA4(acc[i], a[i].x, b[0]);
            FMA4(acc[i], a[i].y, b[1]);
            FMA4(acc[i], a[i].z, b[2]);
            FMA4(acc[i], a[i].w, b[3]);
        }
    }
}
__device__ __forceinline__ void compute16_dual(
    const float (*__restrict__ A)[20], const float (*__restrict__ B1)[68],
    const float (*__restrict__ B2)[68],
    int ty, int tx, float accg[4][4], float acct[4][4])
{
#pragma unroll
    for (int kq = 0; kq < 16; kq += 4) {
        float4 a[4], b[4], c[4];
#pragma unroll
        for (int i = 0; i < 4; i++) a[i] = *(const float4*)&A[ty * 4 + i][kq];
#pragma unroll
        for (int kk = 0; kk < 4; kk++) {
            b[kk] = *(const float4*)&B1[kq + kk][tx * 4];
            c[kk] = *(const float4*)&B2[kq + kk][tx * 4];
        }
#pragma unroll
        for (int i = 0; i < 4; i++) {
            FMA4(accg[i], a[i].x, b[0]);
            FMA4(accg[i], a[i].y, b[1]);
            FMA4(accg[i], a[i].z, b[2]);
            FMA4(accg[i], a[i].w, b[3]);
            FMA4(acct[i], a[i].x, c[0]);
            FMA4(acct[i], a[i].y, c[1]);
            FMA4(acct[i], a[i].z, c[2]);
            FMA4(acct[i], a[i].w, c[3]);
        }
    }
}

// ---------------- 64x64x16 double-buffered fp32 mainloop ----------------
__device__ __forceinline__ void gemm_mainloop64(
    const float* __restrict__ A, int lda,
    const float* __restrict__ B, int ldb,
    int K, int m0, int n0, float acc[4][4])
{
    __shared__ float As[2][64][20];
    __shared__ float Bs[2][16][68];
    const int t = threadIdx.x;
    const int arow = t >> 2, ac4 = (t & 3) * 4;
    const int brow = t >> 4, bc4 = (t & 15) * 4;
    const int tx = t & 15, ty = t >> 4;
    const float* Ag = A + (size_t)(m0 + arow) * lda + ac4;
    const float* Bg = B + (size_t)brow * ldb + n0 + bc4;

    cp16(&As[0][arow][ac4], Ag);
    cp16(&Bs[0][brow][bc4], Bg);
    cp_commit();
    const int nIt = K / 16;
    for (int it = 0; it < nIt; ++it) {
        const int st = it & 1;
        if (it + 1 < nIt) {
            cp16(&As[st ^ 1][arow][ac4], Ag + (it + 1) * 16);
            cp16(&Bs[st ^ 1][brow][bc4], Bg + (size_t)(it + 1) * 16 * ldb);
            cp_commit();
            cp_wait1();
        } else cp_wait0();
        __syncthreads();
        compute16(As[st], Bs[st], ty, tx, acc);
        __syncthreads();
    }
}

// ---------------- prep: tiled transpose Wm, copy Wg top, detect mask layout ----------------
__global__ void prep_k(const float* __restrict__ Wm, const float* __restrict__ Wg,
                       const unsigned* __restrict__ mp) {
    __shared__ float S[32][33];
    int bid = blockIdx.x, t = threadIdx.x;
    if (bid < 64) {
        int tr = bid >> 3, tc = bid & 7;
        int r = t >> 3, c4 = (t & 7) * 4;
        float4 v = *(const float4*)&Wm[(size_t)(tr * 32 + r) * 256 + tc * 32 + c4];
        S[r][c4 + 0] = v.x; S[r][c4 + 1] = v.y; S[r][c4 + 2] = v.z; S[r][c4 + 3] = v.w;
        __syncthreads();
        float4 o;
        o.x = S[c4 + 0][r]; o.y = S[c4 + 1][r]; o.z = S[c4 + 2][r]; o.w = S[c4 + 3][r];
        *(float4*)&g_WmT[(size_t)(tc * 32 + r) * 256 + tr * 32 + c4] = o;
    } else if (bid < 128) {
        int idx = (bid - 64) * 1024 + t * 4;
        *(float4*)&g_Wgfull[idx] = *(const float4*)&Wg[idx];
    } else {
        unsigned m = 0;
        for (int i = (bid - 128) * 256 + t; i < 102400; i += 64 * 256) {
            unsigned wv = mp[i];
            if (wv & 0x000000FFu) m |= 1;
            if (wv & 0x0000FF00u) m |= 2;
            if (wv & 0x00FF0000u) m |= 4;
            if (wv & 0xFF000000u) m |= 8;
        }
#pragma unroll
        for (int o = 16; o > 0; o >>= 1) m |= __shfl_down_sync(0xffffffffu, m, o);
        if ((t & 31) == 0 && m) {
            if (m & 1) atomicOr(&g_flags[0], 1);
            if (m & 2) atomicOr(&g_flags[1], 1);
            if (m & 4) atomicOr(&g_flags[2], 1);
            if (m & 8) atomicOr(&g_flags[3], 1);
        }
    }
}

// ---------------- pre_all: m_init GEMM + 3 weight-fold GEMMs, 64x64 tiles, one launch ----------------
// grid (4, 44): y<32 -> m_init; 32..35 Wkm; 36..39 Wm@Wg_bot; 40..43 Wm@Wt
__global__ void __launch_bounds__(256) pre_all_k(
    const float* __restrict__ r_emb, const float* __restrict__ Wi,
    const float* __restrict__ bi, const float* __restrict__ Wk,
    const float* __restrict__ Wm, const float* __restrict__ Wg,
    const float* __restrict__ Wt)
{
    const int yy = blockIdx.y;
    const float* A; const float* B; float* C; int ldc, m0;
    const float* bias = nullptr;
    if (yy < 32)      { A = r_emb; B = Wi;         C = g_cat;            ldc = 512; m0 = yy * 64; bias = bi; }
    else if (yy < 36) { A = Wk;    B = g_WmT;      C = g_Wkm;            ldc = 256; m0 = (yy - 32) * 64; }
    else if (yy < 40) { A = Wm;    B = Wg + 65536; C = g_Wgfull + 65536; ldc = 256; m0 = (yy - 36) * 64; }
    else              { A = Wm;    B = Wt;         C = g_Wmt;            ldc = 256; m0 = (yy - 40) * 64; }
    const int n0 = blockIdx.x * 64;
    float acc[4][4]; ZERO44(acc);
    gemm_mainloop64(A, 256, B, 256, 256, m0, n0, acc);
    const int tx = threadIdx.x & 15, ty = threadIdx.x >> 4;
#pragma unroll
    for (int i = 0; i < 4; i++) {
        int gm = m0 + ty * 4 + i;
#pragma unroll
        for (int j = 0; j < 4; j++) {
            int gn = n0 + tx * 4 + j;
            float v = acc[i][j];
            if (bias) v += bias[gn];
            C[(size_t)gm * ldc + gn] = v;
        }
    }
}

// ---------------- gemm1b: v = m_init @ Wkm, 64x64 tiles ----------------
__global__ void __launch_bounds__(256) gemm1b_k() {
    int m0 = blockIdx.y * 64, n0 = blockIdx.x * 64;
    float acc[4][4]; ZERO44(acc);
    gemm_mainloop64(g_cat, 512, g_Wkm, 256, 256, m0, n0, acc);
    const int tx = threadIdx.x & 15, ty = threadIdx.x >> 4;
#pragma unroll
    for (int i = 0; i < 4; i++)
#pragma unroll
        for (int j = 0; j < 4; j++)
            g_v[(size_t)(m0 + ty * 4 + i) * 256 + n0 + tx * 4 + j] = acc[i][j];
}

// ---------------- attention part 1: 4 independent CTAs per batch, 50 rows each (round-10) ----------------
__global__ void __launch_bounds__(256) attn_part_k(
    const float* __restrict__ nb_rel,
    const float* __restrict__ delta_t,
    const void*  __restrict__ maskp,
    const float* __restrict__ lgam)
{
    extern __shared__ float TILE[];                 // 50x256 fp32 = 51200 B
    __shared__ float SA[56];
    __shared__ float RED[256];
    __shared__ __align__(8) unsigned long long MB[2];
    const int t = threadIdx.x;
    const int bid = blockIdx.x;
    const int b = bid >> 2, quart = bid & 3;
    const int w = t >> 5, l = t & 31;

    const unsigned tile_s = (unsigned)__cvta_generic_to_shared(TILE);
    const unsigned mb_s   = (unsigned)__cvta_generic_to_shared(MB);

    if (t < 2) mbar_init(mb_s + t * 8, 1);
    __syncthreads();
    if (t == 0) {
        const char* src = (const char*)(nb_rel + (size_t)b * Nn_ * 256 + (size_t)quart * 50 * 256);
#pragma unroll
        for (int c = 0; c < 2; c++) {               // 2 chunks x 25 rows x 1024B
            mbar_expect_tx(mb_s + c * 8, 25600u);
            tma_bulk_1d(tile_s + c * 25600u, src + (size_t)c * 25600u, 25600u, mb_s + c * 8);
        }
    }

    float vr[8];
#pragma unroll
    for (int k = 0; k < 8; k++) vr[k] = g_v[(size_t)b * 256 + k * 32 + l];
    float gamma = expf(lgam[0]);
    int f0 = g_flags[0], f1 = g_flags[1], f2 = g_flags[2], f3 = g_flags[3];
    int mode = f1 ? 0 : ((f2 | f3) ? 2 : (f0 ? 1 : 0));

    // 4 warps per 25-row chunk: h=0 -> 7 rows, h=1..3 -> 6 rows
    {
        const int c = w >> 2, h = w & 3;
        const int base = c * 25 + (h == 0 ? 0 : 6 * h + 1);
        const int cnt = (h == 0) ? 7 : 6;
        mbar_wait_p0(mb_s + c * 8);
        for (int j = 0; j < cnt; j++) {
            int n = base + j;
            float s = 0.f;
#pragma unroll
            for (int k = 0; k < 8; k++)
                s = fmaf(TILE[n * 256 + k * 32 + l], vr[k], s);
#pragma unroll
            for (int o = 16; o > 0; o >>= 1) s += __shfl_down_sync(0xffffffffu, s, o);
            if (l == 0) SA[n] = s * 0.0625f;        // 1/sqrt(256)
        }
    }
    __syncthreads();

    // local av: masked rows get FILLV (exact partial-softmax semantics)
    float av = FILLV;
    if (t < 50) {
        size_t mi = (size_t)b * Nn_ + quart * 50 + t;
        int m;
        if (mode == 0)      m = ((const unsigned char*)maskp)[mi] != 0;
        else if (mode == 1) m = ((const int*)maskp)[mi] != 0;
        else                m = (((const float*)maskp)[mi] != 0.f);
        if (m) {
            float term = fmaxf(-gamma * fmaxf(delta_t[mi], 0.f), -10.f);
            av = SA[t] + term;
        }
    }
    RED[t] = (t < 50) ? av : -1e30f;
    __syncthreads();
    for (int s = 128; s > 0; s >>= 1) { if (t < s) RED[t] = fmaxf(RED[t], RED[t + s]); __syncthreads(); }
    float m0 = RED[0];
    __syncthreads();
    float ex = (t < 50) ? expf(av - m0) : 0.f;
    RED[t] = ex;
    __syncthreads();
    for (int s = 128; s > 0; s >>= 1) { if (t < s) RED[t] += RED[t + s]; __syncthreads(); }
    float s0 = RED[0];
    if (t < 50) SA[t] = ex;                         // unnormalized weights
    __syncthreads();

    // partial c over 50 rows (unnormalized)
    float c0 = 0.f, c1 = 0.f;
#pragma unroll 5
    for (int n = 0; n < 50; n += 2) {
        c0 = fmaf(SA[n],     TILE[n * 256 + t],       c0);
        c1 = fmaf(SA[n + 1], TILE[(n + 1) * 256 + t], c1);
    }
    g_pc[(size_t)bid * 256 + t] = c0 + c1;
    if (t == 0) g_pm[bid] = make_float2(m0, s0);
}

// ---------------- attention part 2: combine 4 quarters exactly ----------------
__global__ void __launch_bounds__(256) attn_fin_k() {
    const int b = blockIdx.x, t = threadIdx.x;
    float2 p0 = g_pm[4 * b], p1 = g_pm[4 * b + 1], p2 = g_pm[4 * b + 2], p3 = g_pm[4 * b + 3];
    float M = fmaxf(fmaxf(p0.x, p1.x), fmaxf(p2.x, p3.x));
    float sc0 = expf(p0.x - M), sc1 = expf(p1.x - M), sc2 = expf(p2.x - M), sc3 = expf(p3.x - M);
    float inv = 1.f / (sc0 * p0.y + sc1 * p1.y + sc2 * p2.y + sc3 * p3.y);
    float c = (sc0 * g_pc[(size_t)(4 * b) * 256 + t] + sc1 * g_pc[(size_t)(4 * b + 1) * 256 + t]
             + sc2 * g_pc[(size_t)(4 * b + 2) * 256 + t] + sc3 * g_pc[(size_t)(4 * b + 3) * 256 + t]) * inv;
    g_cat[(size_t)b * 512 + 256 + t] = c;
}

// ---------------- GEMM2: gg = cat@Wgf (K=512) & t = c@Wmt (K=256), gate epilogue ----------------
__global__ void __launch_bounds__(256) gemm2_k(
    const float* __restrict__ bg, const float* __restrict__ bt)
{
    __shared__ float As [2][64][20];
    __shared__ float B1s[2][16][68];
    __shared__ float B2s[2][16][68];
    const int t = threadIdx.x;
    const int arow = t >> 2, ac4 = (t & 3) * 4;
    const int brow = t >> 4, bc4 = (t & 15) * 4;
    const int tx = t & 15, ty = t >> 4;
    const int m0 = blockIdx.y * 64, n0 = blockIdx.x * 64;

    const float* Ag  = g_cat    + (size_t)(m0 + arow) * 512 + ac4;
    const float* B1g = g_Wgfull + (size_t)brow * 256 + n0 + bc4;
    const float* B2g = g_Wmt    + (size_t)brow * 256 + n0 + bc4;

    float accg[4][4], acct[4][4];
    ZERO44(accg); ZERO44(acct);

    cp16(&As[0][arow][ac4], Ag);
    cp16(&B1s[0][brow][bc4], B1g);
    cp_commit();
    const int nIt = 32;
    for (int it = 0; it < nIt; ++it) {
        const int st = it & 1;
        if (it + 1 < nIt) {
            int kb = (it + 1) * 16;
            cp16(&As[st ^ 1][arow][ac4], Ag + kb);
            cp16(&B1s[st ^ 1][brow][bc4], B1g + (size_t)kb * 256);
            if (kb >= 256)
                cp16(&B2s[st ^ 1][brow][bc4], B2g + (size_t)(kb - 256) * 256);
            cp_commit();
            cp_wait1();
        } else cp_wait0();
        __syncthreads();
        if (it < 16) compute16(As[st], B1s[st], ty, tx, accg);
        else         compute16_dual(As[st], B1s[st], B2s[st], ty, tx, accg, acct);
        __syncthreads();
    }

#pragma unroll
    for (int i = 0; i < 4; i++) {
        int gm = m0 + ty * 4 + i;
#pragma unroll
        for (int j = 0; j < 4; j++) {
            int gn = n0 + tx * 4 + j;
            float gate = 1.f / (1.f + expf(-(accg[i][j] + bg[gn])));
            float th = tanhf(acct[i][j] + bt[gn]);
            g_mo[(size_t)gm * 256 + gn] = gate * th + (1.f - gate) * g_cat[(size_t)gm * 512 + gn];
        }
    }
}

// ---------------- GEMM3: y = m_out @ Wo + bo, 64x64 tiles ----------------
__global__ void __launch_bounds__(256) gemm3_k(
    const float* __restrict__ Wo, const float* __restrict__ bo)
{
    int m0 = blockIdx.y * 64, n0 = blockIdx.x * 64;
    float acc[4][4]; ZERO44(acc);
    gemm_mainloop64(g_mo, 256, Wo, 512, 256, m0, n0, acc);
    const int tx = threadIdx.x & 15, ty = threadIdx.x >> 4;
#pragma unroll
    for (int i = 0; i < 4; i++)
#pragma unroll
        for (int j = 0; j < 4; j++)
            g_y[(size_t)(m0 + ty * 4 + i) * 512 + n0 + tx * 4 + j] = acc[i][j] + bo[n0 + tx * 4 + j];
}

// ---------------- layernorm ----------------
__global__ void __launch_bounds__(256) ln_k(
    const float* __restrict__ g, const float* __restrict__ bta, float* __restrict__ out)
{
    __shared__ float RS[256], RQ[256];
    const int t = threadIdx.x, b = blockIdx.x;
    float a = g_y[(size_t)b * 512 + t];
    float c = g_y[(size_t)b * 512 + 256 + t];
    RS[t] = a + c;
    RQ[t] = a * a + c * c;
    __syncthreads();
    for (int s = 128; s > 0; s >>= 1) {
        if (t < s) { RS[t] += RS[t + s]; RQ[t] += RQ[t + s]; }
        __syncthreads();
    }
    float mu = RS[0] * (1.f / 512.f);
    float var = RQ[0] * (1.f / 512.f) - mu * mu;
    float inv = rsqrtf(var + 1e-5f);
    out[(size_t)b * 512 + t]       = (a - mu) * inv * g[t] + bta[t];
    out[(size_t)b * 512 + 256 + t] = (c - mu) * inv * g[t + 256] + bta[t + 256];
}

// ---------------- launch ----------------
extern "C" void kernel_launch(void* const* d_in, const int* in_sizes, int n_in,
                              void* d_out, int out_size) {
    const float* nb_rel  = (const float*)d_in[0];
    const float* delta_t = (const float*)d_in[1];
    const float* r_emb   = (const float*)d_in[2];
    const void*  maskp   = d_in[3];
    const float* Wi = (const float*)d_in[4];
    const float* bi = (const float*)d_in[5];
    const float* Wm = (const float*)d_in[6];
    const float* Wk = (const float*)d_in[7];
    const float* lg = (const float*)d_in[8];
    const float* Wg = (const float*)d_in[9];
    const float* bg = (const float*)d_in[10];
    const float* Wt = (const float*)d_in[11];
    const float* bt = (const float*)d_in[12];
    const float* Wo = (const float*)d_in[13];
    const float* bo = (const float*)d_in[14];
    const float* lng = (const float*)d_in[15];
    const float* lnb = (const float*)d_in[16];
    float* out = (float*)d_out;

    cudaFuncSetAttribute(attn_part_k, cudaFuncAttributeMaxDynamicSharedMemorySize, 51200);

    prep_k<<<192, 256>>>(Wm, Wg, (const unsigned*)maskp);
    pre_all_k<<<dim3(4, 44), 256>>>(r_emb, Wi, bi, Wk, Wm, Wg, Wt);
    gemm1b_k<<<dim3(4, 32), 256>>>();
    attn_part_k<<<Bsz * 4, 256, 51200>>>(nb_rel, delta_t, maskp, lg);
    attn_fin_k<<<Bsz, 256>>>();
    gemm2_k<<<dim3(4, 32), 256>>>(bg, bt);
    gemm3_k<<<dim3(8, 32), 256>>>(Wo, bo);
    ln_k<<<Bsz, 256>>>(lng, lnb, out);
}